// round 6
// baseline (speedup 1.0000x reference)
#include <cuda_runtime.h>
#include <math.h>
#include <stdint.h>

#define NDIM     128
#define TROWS    60
#define NWARPS   4
#define RPW      15      // rows per warp
#define NTHREADS 128
#define FULLMASK 0xFFFFFFFFu

// LUT layout: c1[0:64) s1[64:128) c2[128:192) s2[192:256) c3[256:320) s3[320:384)
struct LutParams { float v[384]; };

// Degree-15 odd minimax atan on [0,1] + octant fixup; abs err ~1e-6.
__device__ __forceinline__ float fast_atan2f(float y, float x) {
    float ax = fabsf(x), ay = fabsf(y);
    float mx = fmaxf(ax, ay), mn = fminf(ax, ay);
    float t  = __fdividef(mn, mx);
    float t2 = t * t;
    float p  = -0.0040540580f;
    p = fmaf(p, t2,  0.0218612288f);
    p = fmaf(p, t2, -0.0559098861f);
    p = fmaf(p, t2,  0.0964200441f);
    p = fmaf(p, t2, -0.1390853351f);
    p = fmaf(p, t2,  0.1994653599f);
    p = fmaf(p, t2, -0.3332985605f);
    p = fmaf(p, t2,  0.9999993329f);
    float a = p * t;
    if (ay > ax)   a = 1.57079632679489662f - a;
    if (x < 0.0f)  a = 3.14159265358979323f - a;
    return copysignf(a, y);
}

// branchless fast sqrt: h * rsqrt(max(h, tiny)); h==0 -> 0 * finite = 0
__device__ __forceinline__ float fast_sqrtf(float h) {
    return h * rsqrtf(fmaxf(h, 1e-38f));
}

__global__ __launch_bounds__(NTHREADS, 6)
void nautilus_main(const float* __restrict__ x, float* __restrict__ out,
                   const LutParams lp) {
    __shared__ float s_lut[384];
    __shared__ float s_tile[TROWS * NDIM];       // 30720 B: polar values
    __shared__ float s_pmin[NWARPS][NDIM];       // per-warp partial min
    __shared__ float s_pmax[NWARPS][NDIM];

    const int tid = threadIdx.x;
    const int w   = tid >> 5;
    const int l   = tid & 31;
    const size_t base = (size_t)blockIdx.x * (size_t)(TROWS * NDIM);

    // stage LUT param -> smem (3 loads/thread)
    #pragma unroll
    for (int i = tid; i < 384; i += NTHREADS) s_lut[i] = lp.v[i];
    __syncthreads();

    // ---- per-thread rotation constants (uniform across rows) ----
    float c1a = s_lut[2 * l],       s1a = s_lut[64 + 2 * l];
    float c1b = s_lut[2 * l + 1],   s1b = s_lut[64 + 2 * l + 1];
    float cwi = s_lut[128 + 2 * l], swi = s_lut[192 + 2 * l];      // L2 within: k=2l
    // L2 cross coefficients; edge lanes get identity so no predication is needed:
    //   lane 31: t3 = v3*1 - nb*0 = v3 ;  lane 0: t0 = na*0 + v0*1 = v0
    float crr = (l < 31) ? s_lut[128 + 2 * l + 1] : 1.0f;
    float srr = (l < 31) ? s_lut[192 + 2 * l + 1] : 0.0f;
    float cll = (l > 0)  ? s_lut[128 + 2 * l - 1] : 1.0f;
    float sll = (l > 0)  ? s_lut[192 + 2 * l - 1] : 0.0f;
    const bool iside = ((l & 8) == 0);
    int ilane = l & ~8;                                             // i-side lane of xor-8 pair
    float c3v[4], s3v[4];
    #pragma unroll
    for (int q = 0; q < 4; q++) {
        int e = 4 * ilane + q;                 // i-side element index
        int m = (e >= 64) ? (e - 32) : e;      // LUT slot
        c3v[q] = s_lut[256 + m];
        // fold the side into the sign: i-side: v*c - p*s ; j-side: v*c + p*s
        float s3 = s_lut[320 + m];
        s3v[q] = iside ? -s3 : s3;
    }

    float mn0 =  INFINITY, mn1 =  INFINITY, mn2 =  INFINITY, mn3 =  INFINITY;
    float mx0 = -INFINITY, mx1 = -INFINITY, mx2 = -INFINITY, mx3 = -INFINITY;

    // ---- pass 1: load, rotate, polar, min/max, stash polar in smem ----
    #pragma unroll
    for (int i = 0; i < RPW; i++) {
        const int r = w + 4 * i;               // warp-interleaved rows
        float4 v = *(const float4*)(x + base + (size_t)(r * NDIM + 4 * l));
        float v0 = v.x, v1 = v.y, v2 = v.z, v3 = v.w;
        float a, b;

        // layer 1: (2k, 2k+1)
        a = v0; b = v1; v0 = a * c1a - b * s1a; v1 = a * s1a + b * c1a;
        a = v2; b = v3; v2 = a * c1b - b * s1b; v3 = a * s1b + b * c1b;

        // layer 2 within-thread: (4l+1, 4l+2), k=2l
        a = v1; b = v2; v1 = a * cwi - b * swi; v2 = a * swi + b * cwi;

        // layer 2 cross-thread: (4l+3, 4l+4), k=2l+1 — branchless (edge coeffs = identity)
        float nb = __shfl_down_sync(FULLMASK, v0, 1);  // neighbor's v0
        float na = __shfl_up_sync(FULLMASK, v3, 1);    // neighbor's v3
        v3 = v3 * crr - nb * srr;
        v0 = na * sll + v0 * cll;

        // layer 3: (k, k+32) via shfl.xor 8, branch-free (sign folded into s3v)
        float p0 = __shfl_xor_sync(FULLMASK, v0, 8);
        float p1 = __shfl_xor_sync(FULLMASK, v1, 8);
        float p2 = __shfl_xor_sync(FULLMASK, v2, 8);
        float p3 = __shfl_xor_sync(FULLMASK, v3, 8);
        v0 = fmaf(p0, s3v[0], v0 * c3v[0]);
        v1 = fmaf(p1, s3v[1], v1 * c3v[1]);
        v2 = fmaf(p2, s3v[2], v2 * c3v[2]);
        v3 = fmaf(p3, s3v[3], v3 * c3v[3]);

        // polar: (even, odd) pairs are intra-thread
        float h0  = fmaf(v0, v0, v1 * v1);
        float h1  = fmaf(v2, v2, v3 * v3);
        float r0  = fast_sqrtf(h0);
        float r1  = fast_sqrtf(h1);
        float th0 = fast_atan2f(v1, v0);
        float th1 = fast_atan2f(v3, v2);

        mn0 = fminf(mn0, r0);  mx0 = fmaxf(mx0, r0);
        mn1 = fminf(mn1, th0); mx1 = fmaxf(mx1, th0);
        mn2 = fminf(mn2, r1);  mx2 = fmaxf(mx2, r1);
        mn3 = fminf(mn3, th1); mx3 = fmaxf(mx3, th1);

        *(float4*)&s_tile[r * NDIM + 4 * l] = make_float4(r0, th0, r1, th1);
    }

    *(float4*)&s_pmin[w][4 * l] = make_float4(mn0, mn1, mn2, mn3);
    *(float4*)&s_pmax[w][4 * l] = make_float4(mx0, mx1, mx2, mx3);
    __syncthreads();

    // single-barrier reduction: every thread combines the 4 warp partials directly
    float4 a0 = *(const float4*)&s_pmin[0][4 * l];
    float4 a1 = *(const float4*)&s_pmin[1][4 * l];
    float4 a2 = *(const float4*)&s_pmin[2][4 * l];
    float4 a3 = *(const float4*)&s_pmin[3][4 * l];
    float4 b0 = *(const float4*)&s_pmax[0][4 * l];
    float4 b1 = *(const float4*)&s_pmax[1][4 * l];
    float4 b2 = *(const float4*)&s_pmax[2][4 * l];
    float4 b3 = *(const float4*)&s_pmax[3][4 * l];
    float cmnv[4], cmxv[4];
    cmnv[0] = fminf(fminf(a0.x, a1.x), fminf(a2.x, a3.x));
    cmnv[1] = fminf(fminf(a0.y, a1.y), fminf(a2.y, a3.y));
    cmnv[2] = fminf(fminf(a0.z, a1.z), fminf(a2.z, a3.z));
    cmnv[3] = fminf(fminf(a0.w, a1.w), fminf(a2.w, a3.w));
    cmxv[0] = fmaxf(fmaxf(b0.x, b1.x), fmaxf(b2.x, b3.x));
    cmxv[1] = fmaxf(fmaxf(b0.y, b1.y), fmaxf(b2.y, b3.y));
    cmxv[2] = fmaxf(fmaxf(b0.z, b1.z), fmaxf(b2.z, b3.z));
    cmxv[3] = fmaxf(fmaxf(b0.w, b1.w), fmaxf(b2.w, b3.w));

    // precompute per-thread quantization constants (4 IEEE divs total/thread)
    float scale7[4], nm7[4], q14[4], halfmn[4];
    #pragma unroll
    for (int q = 0; q < 4; q++) {
        float cmn = cmnv[q];
        float crg = fmaxf(cmxv[q] - cmn, 1e-8f);
        scale7[q] = 7.0f / crg;            // (p-mn)*scale7 == norm*7
        nm7[q]    = -cmn * scale7[q];      // norm7 = fma(p, scale7, nm7)
        q14[q]    = crg / 14.0f;           // 0.5 * (crg/7)
        halfmn[q] = 0.5f * cmn;
    }

    // ---- pass 2: quantize + residual correction, write out ----
    // corrected = dq + 0.5*(p-dq) = 0.5*p + 0.5*dq = fma(qv, crg/14, fma(0.5,p, 0.5*mn))
    float* op = out + base;
    #pragma unroll
    for (int i = 0; i < RPW; i++) {
        const int r = w + 4 * i;
        float4 p = *(const float4*)&s_tile[r * NDIM + 4 * l];
        float pv[4] = {p.x, p.y, p.z, p.w};
        float res[4];
        #pragma unroll
        for (int q = 0; q < 4; q++) {
            float norm7 = fmaf(pv[q], scale7[q], nm7[q]);  // in [0, 7] by construction
            float qv    = rintf(norm7);                    // half-to-even, lands in [0,7]
            res[q] = fmaf(qv, q14[q], fmaf(0.5f, pv[q], halfmn[q]));
        }
        *(float4*)(op + (size_t)(r * NDIM + 4 * l)) = make_float4(res[0], res[1], res[2], res[3]);
    }
}

static void build_lut_host(LutParams* p) {
    const double PHI = 1.6180339887498948482045868343656;
    const double GA  = 6.2831853071795864769252867665590 / (PHI * PHI);
    for (int k = 0; k < 64; k++) {
        double a1 = GA * (double)(k + 1);
        p->v[k]        = (float)cos(a1);
        p->v[64 + k]   = (float)sin(a1);
        if (k < 63) {
            double a2 = GA * (double)(k + 1) * PHI;
            p->v[128 + k] = (float)cos(a2);
            p->v[192 + k] = (float)sin(a2);
        } else {
            p->v[128 + k] = 0.0f;
            p->v[192 + k] = 0.0f;
        }
        int kk = (k < 32) ? k : (k + 32);   // layer3 accepted ks: 0..31, 64..95
        double a3 = GA * (double)(kk + 1) * PHI * PHI;
        p->v[256 + k] = (float)cos(a3);
        p->v[320 + k] = (float)sin(a3);
    }
}

extern "C" void kernel_launch(void* const* d_in, const int* in_sizes, int n_in,
                              void* d_out, int out_size) {
    const float* x = (const float*)d_in[0];
    float* out = (float*)d_out;
    int nrows  = in_sizes[0] / NDIM;
    int ntiles = nrows / TROWS;
    LutParams lp;
    build_lut_host(&lp);                 // host-side, no device work
    nautilus_main<<<ntiles, NTHREADS>>>(x, out, lp);
}

// round 7
// speedup vs baseline: 1.1467x; 1.1467x over previous
#include <cuda_runtime.h>
#include <cuda_pipeline.h>
#include <math.h>
#include <stdint.h>

#define NDIM     128
#define TROWS    60
#define NWARPS   4
#define RPW      15      // rows per warp
#define NTHREADS 128
#define FULLMASK 0xFFFFFFFFu

// LUT layout: c1[0:64) s1[64:128) c2[128:192) s2[192:256) c3[256:320) s3[320:384)
struct LutParams { float v[384]; };

// Degree-15 odd minimax atan on [0,1] + octant fixup; abs err ~1e-6.
__device__ __forceinline__ float fast_atan2f(float y, float x) {
    float ax = fabsf(x), ay = fabsf(y);
    float mx = fmaxf(ax, ay), mn = fminf(ax, ay);
    float t  = __fdividef(mn, mx);
    float t2 = t * t;
    float p  = -0.0040540580f;
    p = fmaf(p, t2,  0.0218612288f);
    p = fmaf(p, t2, -0.0559098861f);
    p = fmaf(p, t2,  0.0964200441f);
    p = fmaf(p, t2, -0.1390853351f);
    p = fmaf(p, t2,  0.1994653599f);
    p = fmaf(p, t2, -0.3332985605f);
    p = fmaf(p, t2,  0.9999993329f);
    float a = p * t;
    if (ay > ax)   a = 1.57079632679489662f - a;
    if (x < 0.0f)  a = 3.14159265358979323f - a;
    return copysignf(a, y);
}

// branchless fast sqrt: h * rsqrt(max(h, tiny)); h==0 -> 0 * finite = 0
__device__ __forceinline__ float fast_sqrtf(float h) {
    return h * rsqrtf(fmaxf(h, 1e-38f));
}

__global__ __launch_bounds__(NTHREADS, 6)
void nautilus_main(const float* __restrict__ x, float* __restrict__ out,
                   const LutParams lp) {
    __shared__ float s_lut[384];
    __shared__ float s_tile[TROWS * NDIM];       // 30720 B: raw x, overwritten in place by polar
    __shared__ float s_pmin[NWARPS][NDIM];       // per-warp partial min
    __shared__ float s_pmax[NWARPS][NDIM];

    const int tid = threadIdx.x;
    const int w   = tid >> 5;
    const int l   = tid & 31;
    const size_t base = (size_t)blockIdx.x * (size_t)(TROWS * NDIM);

    // ---- front-batch all 15 row-slice copies gmem->smem (MLP=15, no regs) ----
    #pragma unroll
    for (int i = 0; i < RPW; i++) {
        const int r = w + 4 * i;
        const int off = r * NDIM + 4 * l;
        __pipeline_memcpy_async(&s_tile[off], x + base + off, 16);
        __pipeline_commit();
    }

    // stage LUT param -> smem (3 loads/thread) — overlaps with cp.async flight
    #pragma unroll
    for (int i = tid; i < 384; i += NTHREADS) s_lut[i] = lp.v[i];
    __syncthreads();

    // ---- per-thread rotation constants (uniform across rows) ----
    float c1a = s_lut[2 * l],       s1a = s_lut[64 + 2 * l];
    float c1b = s_lut[2 * l + 1],   s1b = s_lut[64 + 2 * l + 1];
    float cwi = s_lut[128 + 2 * l], swi = s_lut[192 + 2 * l];      // L2 within: k=2l
    // L2 cross coefficients; edge lanes get identity so no predication is needed:
    //   lane 31: t3 = v3*1 - nb*0 = v3 ;  lane 0: t0 = na*0 + v0*1 = v0
    float crr = (l < 31) ? s_lut[128 + 2 * l + 1] : 1.0f;
    float srr = (l < 31) ? s_lut[192 + 2 * l + 1] : 0.0f;
    float cll = (l > 0)  ? s_lut[128 + 2 * l - 1] : 1.0f;
    float sll = (l > 0)  ? s_lut[192 + 2 * l - 1] : 0.0f;
    const bool iside = ((l & 8) == 0);
    int ilane = l & ~8;                                             // i-side lane of xor-8 pair
    float c3v[4], s3v[4];
    #pragma unroll
    for (int q = 0; q < 4; q++) {
        int e = 4 * ilane + q;                 // i-side element index
        int m = (e >= 64) ? (e - 32) : e;      // LUT slot
        c3v[q] = s_lut[256 + m];
        // fold the side into the sign: i-side: v*c - p*s ; j-side: v*c + p*s
        float s3 = s_lut[320 + m];
        s3v[q] = iside ? -s3 : s3;
    }

    float mn0 =  INFINITY, mn1 =  INFINITY, mn2 =  INFINITY, mn3 =  INFINITY;
    float mx0 = -INFINITY, mx1 = -INFINITY, mx2 = -INFINITY, mx3 = -INFINITY;

    // ---- pass 1: rotate, polar, min/max; polar overwrites raw x in place ----
    #pragma unroll
    for (int i = 0; i < RPW; i++) {
        __pipeline_wait_prior(RPW - 1 - i);     // row i's copy (this thread's) is done
        const int r = w + 4 * i;                // warp-interleaved rows
        const int off = r * NDIM + 4 * l;
        float4 v = *(const float4*)&s_tile[off];
        float v0 = v.x, v1 = v.y, v2 = v.z, v3 = v.w;
        float a, b;

        // layer 1: (2k, 2k+1)
        a = v0; b = v1; v0 = a * c1a - b * s1a; v1 = a * s1a + b * c1a;
        a = v2; b = v3; v2 = a * c1b - b * s1b; v3 = a * s1b + b * c1b;

        // layer 2 within-thread: (4l+1, 4l+2), k=2l
        a = v1; b = v2; v1 = a * cwi - b * swi; v2 = a * swi + b * cwi;

        // layer 2 cross-thread: (4l+3, 4l+4), k=2l+1 — branchless (edge coeffs = identity)
        float nb = __shfl_down_sync(FULLMASK, v0, 1);  // neighbor's v0
        float na = __shfl_up_sync(FULLMASK, v3, 1);    // neighbor's v3
        v3 = v3 * crr - nb * srr;
        v0 = na * sll + v0 * cll;

        // layer 3: (k, k+32) via shfl.xor 8, branch-free (sign folded into s3v)
        float p0 = __shfl_xor_sync(FULLMASK, v0, 8);
        float p1 = __shfl_xor_sync(FULLMASK, v1, 8);
        float p2 = __shfl_xor_sync(FULLMASK, v2, 8);
        float p3 = __shfl_xor_sync(FULLMASK, v3, 8);
        v0 = fmaf(p0, s3v[0], v0 * c3v[0]);
        v1 = fmaf(p1, s3v[1], v1 * c3v[1]);
        v2 = fmaf(p2, s3v[2], v2 * c3v[2]);
        v3 = fmaf(p3, s3v[3], v3 * c3v[3]);

        // polar: (even, odd) pairs are intra-thread
        float h0  = fmaf(v0, v0, v1 * v1);
        float h1  = fmaf(v2, v2, v3 * v3);
        float r0  = fast_sqrtf(h0);
        float r1  = fast_sqrtf(h1);
        float th0 = fast_atan2f(v1, v0);
        float th1 = fast_atan2f(v3, v2);

        mn0 = fminf(mn0, r0);  mx0 = fmaxf(mx0, r0);
        mn1 = fminf(mn1, th0); mx1 = fmaxf(mx1, th0);
        mn2 = fminf(mn2, r1);  mx2 = fmaxf(mx2, r1);
        mn3 = fminf(mn3, th1); mx3 = fmaxf(mx3, th1);

        *(float4*)&s_tile[off] = make_float4(r0, th0, r1, th1);
    }

    *(float4*)&s_pmin[w][4 * l] = make_float4(mn0, mn1, mn2, mn3);
    *(float4*)&s_pmax[w][4 * l] = make_float4(mx0, mx1, mx2, mx3);
    __syncthreads();

    // single-barrier reduction: every thread combines the 4 warp partials directly
    float4 a0 = *(const float4*)&s_pmin[0][4 * l];
    float4 a1 = *(const float4*)&s_pmin[1][4 * l];
    float4 a2 = *(const float4*)&s_pmin[2][4 * l];
    float4 a3 = *(const float4*)&s_pmin[3][4 * l];
    float4 b0 = *(const float4*)&s_pmax[0][4 * l];
    float4 b1 = *(const float4*)&s_pmax[1][4 * l];
    float4 b2 = *(const float4*)&s_pmax[2][4 * l];
    float4 b3 = *(const float4*)&s_pmax[3][4 * l];
    float cmnv[4], cmxv[4];
    cmnv[0] = fminf(fminf(a0.x, a1.x), fminf(a2.x, a3.x));
    cmnv[1] = fminf(fminf(a0.y, a1.y), fminf(a2.y, a3.y));
    cmnv[2] = fminf(fminf(a0.z, a1.z), fminf(a2.z, a3.z));
    cmnv[3] = fminf(fminf(a0.w, a1.w), fminf(a2.w, a3.w));
    cmxv[0] = fmaxf(fmaxf(b0.x, b1.x), fmaxf(b2.x, b3.x));
    cmxv[1] = fmaxf(fmaxf(b0.y, b1.y), fmaxf(b2.y, b3.y));
    cmxv[2] = fmaxf(fmaxf(b0.z, b1.z), fmaxf(b2.z, b3.z));
    cmxv[3] = fmaxf(fmaxf(b0.w, b1.w), fmaxf(b2.w, b3.w));

    // precompute per-thread quantization constants (4 IEEE divs total/thread)
    float scale7[4], nm7[4], q14[4], halfmn[4];
    #pragma unroll
    for (int q = 0; q < 4; q++) {
        float cmn = cmnv[q];
        float crg = fmaxf(cmxv[q] - cmn, 1e-8f);
        scale7[q] = 7.0f / crg;            // (p-mn)*scale7 == norm*7
        nm7[q]    = -cmn * scale7[q];      // norm7 = fma(p, scale7, nm7)
        q14[q]    = crg / 14.0f;           // 0.5 * (crg/7)
        halfmn[q] = 0.5f * cmn;
    }

    // ---- pass 2: quantize + residual correction, write out ----
    // corrected = dq + 0.5*(p-dq) = 0.5*p + 0.5*dq = fma(qv, crg/14, fma(0.5,p, 0.5*mn))
    float* op = out + base;
    #pragma unroll
    for (int i = 0; i < RPW; i++) {
        const int r = w + 4 * i;
        float4 p = *(const float4*)&s_tile[r * NDIM + 4 * l];
        float pv[4] = {p.x, p.y, p.z, p.w};
        float res[4];
        #pragma unroll
        for (int q = 0; q < 4; q++) {
            float norm7 = fmaf(pv[q], scale7[q], nm7[q]);  // in [0, 7] by construction
            float qv    = rintf(norm7);                    // half-to-even, lands in [0,7]
            res[q] = fmaf(qv, q14[q], fmaf(0.5f, pv[q], halfmn[q]));
        }
        *(float4*)(op + (size_t)(r * NDIM + 4 * l)) = make_float4(res[0], res[1], res[2], res[3]);
    }
}

static void build_lut_host(LutParams* p) {
    const double PHI = 1.6180339887498948482045868343656;
    const double GA  = 6.2831853071795864769252867665590 / (PHI * PHI);
    for (int k = 0; k < 64; k++) {
        double a1 = GA * (double)(k + 1);
        p->v[k]        = (float)cos(a1);
        p->v[64 + k]   = (float)sin(a1);
        if (k < 63) {
            double a2 = GA * (double)(k + 1) * PHI;
            p->v[128 + k] = (float)cos(a2);
            p->v[192 + k] = (float)sin(a2);
        } else {
            p->v[128 + k] = 0.0f;
            p->v[192 + k] = 0.0f;
        }
        int kk = (k < 32) ? k : (k + 32);   // layer3 accepted ks: 0..31, 64..95
        double a3 = GA * (double)(kk + 1) * PHI * PHI;
        p->v[256 + k] = (float)cos(a3);
        p->v[320 + k] = (float)sin(a3);
    }
}

extern "C" void kernel_launch(void* const* d_in, const int* in_sizes, int n_in,
                              void* d_out, int out_size) {
    const float* x = (const float*)d_in[0];
    float* out = (float*)d_out;
    int nrows  = in_sizes[0] / NDIM;
    int ntiles = nrows / TROWS;
    LutParams lp;
    build_lut_host(&lp);                 // host-side, no device work
    nautilus_main<<<ntiles, NTHREADS>>>(x, out, lp);
}